// round 2
// baseline (speedup 1.0000x reference)
#include <cuda_runtime.h>
#include <cstdint>

// Problem constants (SGC_77584289235646): fixed shapes.
#define IN_DIM   128
#define EMB_DIM  32
#define MAX_NODES 100000

// Ping-pong buffers for h between hops (no cudaMalloc allowed).
// 16B-aligned: we use float4 loads and red.v4 on these.
__device__ __align__(16) float g_hA[(size_t)MAX_NODES * EMB_DIM];
__device__ __align__(16) float g_hB[(size_t)MAX_NODES * EMB_DIM];

// ---------------------------------------------------------------------------
// Kernel 1: h0 = relu(x @ W^T + b)
// One warp per node; lane e computes output channel e.
// ---------------------------------------------------------------------------
__global__ void __launch_bounds__(256)
sgc_transform(const float* __restrict__ x,
              const float* __restrict__ W,
              const float* __restrict__ b,
              float* __restrict__ h,
              int n_nodes)
{
    __shared__ float Wt[IN_DIM][EMB_DIM];   // transposed W: Wt[k][e]
    __shared__ float bs[EMB_DIM];
    __shared__ float xrow[8][IN_DIM];       // 8 warps per block

    for (int i = threadIdx.x; i < EMB_DIM * IN_DIM; i += blockDim.x) {
        int e = i / IN_DIM, k = i % IN_DIM;
        Wt[k][e] = W[i];
    }
    if (threadIdx.x < EMB_DIM) bs[threadIdx.x] = b[threadIdx.x];
    __syncthreads();

    int warp = threadIdx.x >> 5;
    int lane = threadIdx.x & 31;
    int node = blockIdx.x * 8 + warp;
    if (node >= n_nodes) return;

    // Stage x row: 32 lanes x float4 = 128 floats, one coalesced 512B read.
    const float4 xv = reinterpret_cast<const float4*>(x + (size_t)node * IN_DIM)[lane];
    reinterpret_cast<float4*>(xrow[warp])[lane] = xv;
    __syncwarp();

    float acc = 0.f;
    #pragma unroll
    for (int k = 0; k < IN_DIM; ++k)
        acc = fmaf(xrow[warp][k], Wt[k][lane], acc);
    acc += bs[lane];
    h[(size_t)node * EMB_DIM + lane] = fmaxf(acc, 0.f);
}

// ---------------------------------------------------------------------------
// Kernel 2: one hop. 8 threads per edge; thread owns a 16B chunk of the
// 128B embedding row. Gather float4 from h_in[src] (coalesced across the
// 8-thread cluster), scale by w[e], vector-RED into h_out[dst].
// Indices are INT32 (JAX x64 disabled -> randint falls back to int32).
// ---------------------------------------------------------------------------
__global__ void __launch_bounds__(256)
sgc_hop(const float* __restrict__ h_in,
        const int* __restrict__ src,
        const int* __restrict__ dst,
        const float* __restrict__ w,
        float* __restrict__ h_out,
        int n_edges)
{
    int gid = blockIdx.x * blockDim.x + threadIdx.x;
    int e = gid >> 3;          // edge
    int c = gid & 7;           // 16B chunk within the 128B row
    if (e >= n_edges) return;

    int   s  = src[e];
    int   d  = dst[e];
    float wv = w[e];

    const float4 v = reinterpret_cast<const float4*>(h_in + (size_t)s * EMB_DIM)[c];
    float4 m;
    m.x = v.x * wv; m.y = v.y * wv; m.z = v.z * wv; m.w = v.w * wv;

    float* p = h_out + (size_t)d * EMB_DIM + (size_t)c * 4;
    asm volatile("red.global.add.v4.f32 [%0], {%1, %2, %3, %4};"
                 :: "l"(p), "f"(m.x), "f"(m.y), "f"(m.z), "f"(m.w)
                 : "memory");
}

// ---------------------------------------------------------------------------
// Launcher. Inputs (metadata order): x[N,128] f32, W[32,128] f32, b[32] f32,
// w[E] f32, src[E] i32, dst[E] i32, k (scalar). Output: h[N,32] f32.
// ---------------------------------------------------------------------------
extern "C" void kernel_launch(void* const* d_in, const int* in_sizes, int n_in,
                              void* d_out, int out_size)
{
    const float* x   = (const float*)d_in[0];
    const float* W   = (const float*)d_in[1];
    const float* b   = (const float*)d_in[2];
    const float* w   = (const float*)d_in[3];
    const int*   src = (const int*)d_in[4];
    const int*   dst = (const int*)d_in[5];
    float* out = (float*)d_out;

    const int n_nodes = in_sizes[0] / IN_DIM;
    const int n_edges = in_sizes[3];
    const size_t h_bytes = (size_t)n_nodes * EMB_DIM * sizeof(float);

    float* hA = nullptr;
    float* hB = nullptr;
    cudaGetSymbolAddress((void**)&hA, g_hA);
    cudaGetSymbolAddress((void**)&hB, g_hB);

    // h0 = relu(x @ W^T + b) -> hA
    sgc_transform<<<(n_nodes + 7) / 8, 256>>>(x, W, b, hA, n_nodes);

    const long long hop_threads = (long long)n_edges * 8;
    const int hop_blocks = (int)((hop_threads + 255) / 256);

    // hop 1: hA -> hB
    cudaMemsetAsync(hB, 0, h_bytes);
    sgc_hop<<<hop_blocks, 256>>>(hA, src, dst, w, hB, n_edges);

    // hop 2: hB -> hA
    cudaMemsetAsync(hA, 0, h_bytes);
    sgc_hop<<<hop_blocks, 256>>>(hB, src, dst, w, hA, n_edges);

    // hop 3: hA -> out
    cudaMemsetAsync(out, 0, (size_t)out_size * sizeof(float));
    sgc_hop<<<hop_blocks, 256>>>(hA, src, dst, w, out, n_edges);
}

// round 3
// speedup vs baseline: 2.0668x; 2.0668x over previous
#include <cuda_runtime.h>
#include <cstdint>

// Problem constants (SGC_77584289235646): fixed shapes.
#define IN_DIM   128
#define EMB_DIM  32
#define MAX_NODES 100000

// Ping-pong buffers for h between hops (no cudaMalloc allowed).
__device__ __align__(16) float g_hA[(size_t)MAX_NODES * EMB_DIM];
__device__ __align__(16) float g_hB[(size_t)MAX_NODES * EMB_DIM];

// ---------------------------------------------------------------------------
// Kernel 1: h0 = relu(x @ W^T + b)
// Thread-per-node register-tiled GEMM:
//   - 32 fp32 accumulators per thread (one per output channel)
//   - W (32x128 = 16KB) staged once in smem, read as broadcast LDS.128
//   - x row read as 32 sequential float4 LDG.128 per thread (L1 covers the
//     line reuse across the kc loop; total DRAM read = exactly 51.2MB)
// FFMA:LDS = 4:1 -> FFMA-pipe bound (~22us floor chip-wide).
// ---------------------------------------------------------------------------
__global__ void __launch_bounds__(256)
sgc_transform(const float* __restrict__ x,
              const float* __restrict__ W,
              const float* __restrict__ b,
              float* __restrict__ h,
              int n_nodes)
{
    // Ws[e*32 + kc] = W[e][4*kc .. 4*kc+3]
    __shared__ float4 Ws[EMB_DIM * (IN_DIM / 4)];   // 1024 float4 = 16KB
    __shared__ float  bsh[EMB_DIM];

    for (int i = threadIdx.x; i < EMB_DIM * (IN_DIM / 4); i += blockDim.x)
        Ws[i] = reinterpret_cast<const float4*>(W)[i];
    if (threadIdx.x < EMB_DIM) bsh[threadIdx.x] = b[threadIdx.x];
    __syncthreads();

    const int node = blockIdx.x * blockDim.x + threadIdx.x;
    if (node >= n_nodes) return;

    const float4* xr = reinterpret_cast<const float4*>(x + (size_t)node * IN_DIM);

    float acc[EMB_DIM];
    #pragma unroll
    for (int e = 0; e < EMB_DIM; ++e) acc[e] = 0.f;

    #pragma unroll 4
    for (int kc = 0; kc < IN_DIM / 4; ++kc) {
        const float4 xv = xr[kc];
        #pragma unroll
        for (int e = 0; e < EMB_DIM; ++e) {
            const float4 wv = Ws[e * (IN_DIM / 4) + kc];   // warp-broadcast
            acc[e] = fmaf(xv.x, wv.x, acc[e]);
            acc[e] = fmaf(xv.y, wv.y, acc[e]);
            acc[e] = fmaf(xv.z, wv.z, acc[e]);
            acc[e] = fmaf(xv.w, wv.w, acc[e]);
        }
    }

    float4* hp = reinterpret_cast<float4*>(h + (size_t)node * EMB_DIM);
    #pragma unroll
    for (int e = 0; e < EMB_DIM; e += 4) {
        float4 o;
        o.x = fmaxf(acc[e + 0] + bsh[e + 0], 0.f);
        o.y = fmaxf(acc[e + 1] + bsh[e + 1], 0.f);
        o.z = fmaxf(acc[e + 2] + bsh[e + 2], 0.f);
        o.w = fmaxf(acc[e + 3] + bsh[e + 3], 0.f);
        hp[e / 4] = o;
    }
}

// ---------------------------------------------------------------------------
// Kernel 2: one hop. 8 threads per edge; thread owns a 16B chunk of the
// 128B embedding row. Gather float4 from h_in[src] (coalesced across the
// 8-thread cluster), scale by w[e], vector-RED into h_out[dst].
// Near the L2/atomic bandwidth floor (~50us) already.
// ---------------------------------------------------------------------------
__global__ void __launch_bounds__(256)
sgc_hop(const float* __restrict__ h_in,
        const int* __restrict__ src,
        const int* __restrict__ dst,
        const float* __restrict__ w,
        float* __restrict__ h_out,
        int n_edges)
{
    int gid = blockIdx.x * blockDim.x + threadIdx.x;
    int e = gid >> 3;          // edge
    int c = gid & 7;           // 16B chunk within the 128B row
    if (e >= n_edges) return;

    int   s  = src[e];
    int   d  = dst[e];
    float wv = w[e];

    const float4 v = reinterpret_cast<const float4*>(h_in + (size_t)s * EMB_DIM)[c];
    float4 m;
    m.x = v.x * wv; m.y = v.y * wv; m.z = v.z * wv; m.w = v.w * wv;

    float* p = h_out + (size_t)d * EMB_DIM + (size_t)c * 4;
    asm volatile("red.global.add.v4.f32 [%0], {%1, %2, %3, %4};"
                 :: "l"(p), "f"(m.x), "f"(m.y), "f"(m.z), "f"(m.w)
                 : "memory");
}

// ---------------------------------------------------------------------------
// Launcher. Inputs (metadata order): x[N,128] f32, W[32,128] f32, b[32] f32,
// w[E] f32, src[E] i32, dst[E] i32, k (scalar). Output: h[N,32] f32.
// ---------------------------------------------------------------------------
extern "C" void kernel_launch(void* const* d_in, const int* in_sizes, int n_in,
                              void* d_out, int out_size)
{
    const float* x   = (const float*)d_in[0];
    const float* W   = (const float*)d_in[1];
    const float* b   = (const float*)d_in[2];
    const float* w   = (const float*)d_in[3];
    const int*   src = (const int*)d_in[4];
    const int*   dst = (const int*)d_in[5];
    float* out = (float*)d_out;

    const int n_nodes = in_sizes[0] / IN_DIM;
    const int n_edges = in_sizes[3];
    const size_t h_bytes = (size_t)n_nodes * EMB_DIM * sizeof(float);

    float* hA = nullptr;
    float* hB = nullptr;
    cudaGetSymbolAddress((void**)&hA, g_hA);
    cudaGetSymbolAddress((void**)&hB, g_hB);

    // h0 = relu(x @ W^T + b) -> hA
    sgc_transform<<<(n_nodes + 255) / 256, 256>>>(x, W, b, hA, n_nodes);

    const long long hop_threads = (long long)n_edges * 8;
    const int hop_blocks = (int)((hop_threads + 255) / 256);

    // hop 1: hA -> hB
    cudaMemsetAsync(hB, 0, h_bytes);
    sgc_hop<<<hop_blocks, 256>>>(hA, src, dst, w, hB, n_edges);

    // hop 2: hB -> hA
    cudaMemsetAsync(hA, 0, h_bytes);
    sgc_hop<<<hop_blocks, 256>>>(hB, src, dst, w, hA, n_edges);

    // hop 3: hA -> out
    cudaMemsetAsync(out, 0, (size_t)out_size * sizeof(float));
    sgc_hop<<<hop_blocks, 256>>>(hA, src, dst, w, out, n_edges);
}

// round 4
// speedup vs baseline: 2.4318x; 1.1766x over previous
#include <cuda_runtime.h>
#include <cstdint>

// Problem constants (SGC_77584289235646): fixed shapes.
#define IN_DIM    128
#define EMB_DIM   32
#define MAX_NODES 100000
#define MAX_EDGES 1600000
#define SCAN_B    1024          // elements per scan block
#define MAX_SCAN_BLOCKS 128     // supports up to 131072 nodes

// Scratch (no cudaMalloc allowed).
__device__ __align__(16) float g_hA[(size_t)MAX_NODES * EMB_DIM];
__device__ __align__(16) float g_hB[(size_t)MAX_NODES * EMB_DIM];
__device__ int  g_counts [MAX_NODES];
__device__ int  g_offsets[MAX_NODES];
__device__ int  g_cursor [MAX_NODES];
__device__ int  g_spine  [MAX_SCAN_BLOCKS];
__device__ __align__(16) int2 g_edge[MAX_EDGES];   // {src, w-bits} sorted by dst

// ---------------------------------------------------------------------------
// Kernel 1: h0 = relu(x @ W^T + b). Thread-per-node, 32 regs of accumulators,
// W staged in smem (broadcast LDS.128). FFMA-bound, ~25us.
// ---------------------------------------------------------------------------
__global__ void __launch_bounds__(256)
sgc_transform(const float* __restrict__ x,
              const float* __restrict__ W,
              const float* __restrict__ b,
              float* __restrict__ h,
              int n_nodes)
{
    __shared__ float4 Ws[EMB_DIM * (IN_DIM / 4)];   // 16KB
    __shared__ float  bsh[EMB_DIM];

    for (int i = threadIdx.x; i < EMB_DIM * (IN_DIM / 4); i += blockDim.x)
        Ws[i] = reinterpret_cast<const float4*>(W)[i];
    if (threadIdx.x < EMB_DIM) bsh[threadIdx.x] = b[threadIdx.x];
    __syncthreads();

    const int node = blockIdx.x * blockDim.x + threadIdx.x;
    if (node >= n_nodes) return;

    const float4* xr = reinterpret_cast<const float4*>(x + (size_t)node * IN_DIM);

    float acc[EMB_DIM];
    #pragma unroll
    for (int e = 0; e < EMB_DIM; ++e) acc[e] = 0.f;

    #pragma unroll 4
    for (int kc = 0; kc < IN_DIM / 4; ++kc) {
        const float4 xv = xr[kc];
        #pragma unroll
        for (int e = 0; e < EMB_DIM; ++e) {
            const float4 wv = Ws[e * (IN_DIM / 4) + kc];
            acc[e] = fmaf(xv.x, wv.x, acc[e]);
            acc[e] = fmaf(xv.y, wv.y, acc[e]);
            acc[e] = fmaf(xv.z, wv.z, acc[e]);
            acc[e] = fmaf(xv.w, wv.w, acc[e]);
        }
    }

    float4* hp = reinterpret_cast<float4*>(h + (size_t)node * EMB_DIM);
    #pragma unroll
    for (int e = 0; e < EMB_DIM; e += 4) {
        float4 o;
        o.x = fmaxf(acc[e + 0] + bsh[e + 0], 0.f);
        o.y = fmaxf(acc[e + 1] + bsh[e + 1], 0.f);
        o.z = fmaxf(acc[e + 2] + bsh[e + 2], 0.f);
        o.w = fmaxf(acc[e + 3] + bsh[e + 3], 0.f);
        hp[e / 4] = o;
    }
}

// ---------------------------------------------------------------------------
// CSR build: histogram -> 3-kernel exclusive scan -> cursor-scatter.
// ---------------------------------------------------------------------------
__global__ void csr_histogram(const int* __restrict__ dst, int n_edges)
{
    int e = blockIdx.x * blockDim.x + threadIdx.x;
    if (e < n_edges) atomicAdd(&g_counts[dst[e]], 1);
}

// Per-block exclusive scan of counts -> offsets(partial), block totals -> spine.
__global__ void __launch_bounds__(SCAN_B)
csr_scan1(int n)
{
    __shared__ int s[SCAN_B];
    int i = blockIdx.x * SCAN_B + threadIdx.x;
    int v = (i < n) ? g_counts[i] : 0;
    s[threadIdx.x] = v;
    __syncthreads();
    #pragma unroll
    for (int off = 1; off < SCAN_B; off <<= 1) {
        int t = (threadIdx.x >= off) ? s[threadIdx.x - off] : 0;
        __syncthreads();
        s[threadIdx.x] += t;
        __syncthreads();
    }
    int incl = s[threadIdx.x];
    if (i < n) g_offsets[i] = incl - v;            // exclusive within block
    if (threadIdx.x == SCAN_B - 1) g_spine[blockIdx.x] = incl;
}

// Exclusive scan of the spine (one block).
__global__ void __launch_bounds__(MAX_SCAN_BLOCKS)
csr_scan2(int n_blocks)
{
    __shared__ int s[MAX_SCAN_BLOCKS];
    int v = (threadIdx.x < n_blocks) ? g_spine[threadIdx.x] : 0;
    s[threadIdx.x] = v;
    __syncthreads();
    #pragma unroll
    for (int off = 1; off < MAX_SCAN_BLOCKS; off <<= 1) {
        int t = (threadIdx.x >= off) ? s[threadIdx.x - off] : 0;
        __syncthreads();
        s[threadIdx.x] += t;
        __syncthreads();
    }
    if (threadIdx.x < n_blocks) g_spine[threadIdx.x] = s[threadIdx.x] - v;
}

// Add spine; also initialize cursors.
__global__ void __launch_bounds__(SCAN_B)
csr_scan3(int n)
{
    int i = blockIdx.x * SCAN_B + threadIdx.x;
    if (i < n) {
        int o = g_offsets[i] + g_spine[blockIdx.x];
        g_offsets[i] = o;
        g_cursor[i]  = o;
    }
}

__global__ void csr_scatter(const int* __restrict__ src,
                            const int* __restrict__ dst,
                            const float* __restrict__ w,
                            int n_edges)
{
    int e = blockIdx.x * blockDim.x + threadIdx.x;
    if (e >= n_edges) return;
    int pos = atomicAdd(&g_cursor[dst[e]], 1);
    g_edge[pos] = make_int2(src[e], __float_as_int(w[e]));
}

// ---------------------------------------------------------------------------
// Kernel 2: one hop, CSR form (no atomics, no pre-memset).
// 8-thread group per dst node; thread c owns the c-th 16B chunk of the row.
// Loop over the node's edge bin, accumulate h_in[src]*w in a register float4,
// write the chunk once at the end.
// ---------------------------------------------------------------------------
__global__ void __launch_bounds__(256)
sgc_hop_csr(const float* __restrict__ h_in,
            float* __restrict__ h_out,
            int n_nodes)
{
    int gid  = blockIdx.x * blockDim.x + threadIdx.x;
    int node = gid >> 3;
    int c    = gid & 7;
    if (node >= n_nodes) return;

    const int start = g_offsets[node];
    const int cnt   = g_counts[node];
    const int end   = start + cnt;

    float4 acc = make_float4(0.f, 0.f, 0.f, 0.f);

    int j = start;
    for (; j + 1 < end; j += 2) {
        const int2 e0 = g_edge[j];
        const int2 e1 = g_edge[j + 1];
        const float4 v0 = reinterpret_cast<const float4*>(h_in + (size_t)e0.x * EMB_DIM)[c];
        const float4 v1 = reinterpret_cast<const float4*>(h_in + (size_t)e1.x * EMB_DIM)[c];
        const float w0 = __int_as_float(e0.y);
        const float w1 = __int_as_float(e1.y);
        acc.x = fmaf(v0.x, w0, acc.x); acc.y = fmaf(v0.y, w0, acc.y);
        acc.z = fmaf(v0.z, w0, acc.z); acc.w = fmaf(v0.w, w0, acc.w);
        acc.x = fmaf(v1.x, w1, acc.x); acc.y = fmaf(v1.y, w1, acc.y);
        acc.z = fmaf(v1.z, w1, acc.z); acc.w = fmaf(v1.w, w1, acc.w);
    }
    if (j < end) {
        const int2 e0 = g_edge[j];
        const float4 v0 = reinterpret_cast<const float4*>(h_in + (size_t)e0.x * EMB_DIM)[c];
        const float w0 = __int_as_float(e0.y);
        acc.x = fmaf(v0.x, w0, acc.x); acc.y = fmaf(v0.y, w0, acc.y);
        acc.z = fmaf(v0.z, w0, acc.z); acc.w = fmaf(v0.w, w0, acc.w);
    }

    reinterpret_cast<float4*>(h_out + (size_t)node * EMB_DIM)[c] = acc;
}

// ---------------------------------------------------------------------------
// Launcher. Inputs: x[N,128] f32, W[32,128] f32, b[32] f32, w[E] f32,
// src[E] i32, dst[E] i32, k (fixed 3). Output: h[N,32] f32.
// ---------------------------------------------------------------------------
extern "C" void kernel_launch(void* const* d_in, const int* in_sizes, int n_in,
                              void* d_out, int out_size)
{
    const float* x   = (const float*)d_in[0];
    const float* W   = (const float*)d_in[1];
    const float* b   = (const float*)d_in[2];
    const float* w   = (const float*)d_in[3];
    const int*   src = (const int*)d_in[4];
    const int*   dst = (const int*)d_in[5];
    float* out = (float*)d_out;

    const int n_nodes = in_sizes[0] / IN_DIM;
    const int n_edges = in_sizes[3];

    float* hA = nullptr; float* hB = nullptr; int* counts = nullptr;
    cudaGetSymbolAddress((void**)&hA, g_hA);
    cudaGetSymbolAddress((void**)&hB, g_hB);
    cudaGetSymbolAddress((void**)&counts, g_counts);

    // Transform: h0 = relu(x @ W^T + b) -> hA
    sgc_transform<<<(n_nodes + 255) / 256, 256>>>(x, W, b, hA, n_nodes);

    // CSR build (per call; shapes fixed but no caching allowed).
    cudaMemsetAsync(counts, 0, (size_t)n_nodes * sizeof(int));
    csr_histogram<<<(n_edges + 255) / 256, 256>>>(dst, n_edges);
    const int scan_blocks = (n_nodes + SCAN_B - 1) / SCAN_B;
    csr_scan1<<<scan_blocks, SCAN_B>>>(n_nodes);
    csr_scan2<<<1, MAX_SCAN_BLOCKS>>>(scan_blocks);
    csr_scan3<<<scan_blocks, SCAN_B>>>(n_nodes);
    csr_scatter<<<(n_edges + 255) / 256, 256>>>(src, dst, w, n_edges);

    // 3 hops, gather-only (every node written -> no memsets needed).
    const int hop_blocks = (int)(((long long)n_nodes * 8 + 255) / 256);
    sgc_hop_csr<<<hop_blocks, 256>>>(hA, hB, n_nodes);
    sgc_hop_csr<<<hop_blocks, 256>>>(hB, hA, n_nodes);
    sgc_hop_csr<<<hop_blocks, 256>>>(hA, out, n_nodes);
}

// round 5
// speedup vs baseline: 2.4880x; 1.0231x over previous
#include <cuda_runtime.h>
#include <cstdint>

// Problem constants (SGC_77584289235646): fixed shapes.
#define IN_DIM    128
#define EMB_DIM   32
#define MAX_NODES 100000
#define MAX_EDGES 1600000
#define SCAN_B    1024
#define MAX_SCAN_BLOCKS 128
#define CHUNK     16            // edges per 8-thread group in the hop

// Scratch (no cudaMalloc allowed).
__device__ __align__(16) float g_hA[(size_t)MAX_NODES * EMB_DIM];
__device__ __align__(16) float g_hB[(size_t)MAX_NODES * EMB_DIM];
__device__ int  g_counts [MAX_NODES];
__device__ int  g_offsets[MAX_NODES];
__device__ int  g_cursor [MAX_NODES];
__device__ int  g_spine  [MAX_SCAN_BLOCKS];
__device__ __align__(16) int4 g_edge[MAX_EDGES];   // {src, w-bits, dst, 0} sorted by dst

// ---------------------------------------------------------------------------
// Kernel 1: h0 = relu(x @ W^T + b). Thread-per-node, 32 accumulators,
// W staged in smem (broadcast LDS.128). FFMA-bound (~25us).
// ---------------------------------------------------------------------------
__global__ void __launch_bounds__(256)
sgc_transform(const float* __restrict__ x,
              const float* __restrict__ W,
              const float* __restrict__ b,
              float* __restrict__ h,
              int n_nodes)
{
    __shared__ float4 Ws[EMB_DIM * (IN_DIM / 4)];   // 16KB
    __shared__ float  bsh[EMB_DIM];

    for (int i = threadIdx.x; i < EMB_DIM * (IN_DIM / 4); i += blockDim.x)
        Ws[i] = reinterpret_cast<const float4*>(W)[i];
    if (threadIdx.x < EMB_DIM) bsh[threadIdx.x] = b[threadIdx.x];
    __syncthreads();

    const int node = blockIdx.x * blockDim.x + threadIdx.x;
    if (node >= n_nodes) return;

    const float4* xr = reinterpret_cast<const float4*>(x + (size_t)node * IN_DIM);

    float acc[EMB_DIM];
    #pragma unroll
    for (int e = 0; e < EMB_DIM; ++e) acc[e] = 0.f;

    #pragma unroll 4
    for (int kc = 0; kc < IN_DIM / 4; ++kc) {
        const float4 xv = xr[kc];
        #pragma unroll
        for (int e = 0; e < EMB_DIM; ++e) {
            const float4 wv = Ws[e * (IN_DIM / 4) + kc];
            acc[e] = fmaf(xv.x, wv.x, acc[e]);
            acc[e] = fmaf(xv.y, wv.y, acc[e]);
            acc[e] = fmaf(xv.z, wv.z, acc[e]);
            acc[e] = fmaf(xv.w, wv.w, acc[e]);
        }
    }

    float4* hp = reinterpret_cast<float4*>(h + (size_t)node * EMB_DIM);
    #pragma unroll
    for (int e = 0; e < EMB_DIM; e += 4) {
        float4 o;
        o.x = fmaxf(acc[e + 0] + bsh[e + 0], 0.f);
        o.y = fmaxf(acc[e + 1] + bsh[e + 1], 0.f);
        o.z = fmaxf(acc[e + 2] + bsh[e + 2], 0.f);
        o.w = fmaxf(acc[e + 3] + bsh[e + 3], 0.f);
        hp[e / 4] = o;
    }
}

// ---------------------------------------------------------------------------
// CSR build: histogram -> warp-shuffle scan (3 kernels) -> cursor-scatter.
// ---------------------------------------------------------------------------
__global__ void csr_histogram(const int* __restrict__ dst, int n_edges)
{
    int i = (blockIdx.x * blockDim.x + threadIdx.x) * 4;
    if (i + 3 < n_edges) {
        const int4 d = *reinterpret_cast<const int4*>(dst + i);
        atomicAdd(&g_counts[d.x], 1);
        atomicAdd(&g_counts[d.y], 1);
        atomicAdd(&g_counts[d.z], 1);
        atomicAdd(&g_counts[d.w], 1);
    } else {
        for (; i < n_edges; ++i) atomicAdd(&g_counts[dst[i]], 1);
    }
}

// Block-local exclusive scan via warp shuffles; block totals -> spine.
__global__ void __launch_bounds__(SCAN_B)
csr_scan1(int n)
{
    __shared__ int wsum[32];
    const int i    = blockIdx.x * SCAN_B + threadIdx.x;
    const int lane = threadIdx.x & 31;
    const int warp = threadIdx.x >> 5;

    const int v = (i < n) ? g_counts[i] : 0;
    int incl = v;
    #pragma unroll
    for (int off = 1; off < 32; off <<= 1) {
        int t = __shfl_up_sync(0xffffffffu, incl, off);
        if (lane >= off) incl += t;
    }
    if (lane == 31) wsum[warp] = incl;
    __syncthreads();
    if (warp == 0) {
        int s = wsum[lane];
        int si = s;
        #pragma unroll
        for (int off = 1; off < 32; off <<= 1) {
            int t = __shfl_up_sync(0xffffffffu, si, off);
            if (lane >= off) si += t;
        }
        wsum[lane] = si - s;                       // exclusive warp offset
        if (lane == 31) g_spine[blockIdx.x] = si;  // block total
    }
    __syncthreads();
    if (i < n) g_offsets[i] = incl - v + wsum[warp];
}

// Exclusive scan of the spine: one warp, 4 elems per lane (<=128).
__global__ void csr_scan2(int n_blocks)
{
    const int lane = threadIdx.x;
    const int base = lane * 4;
    int v0 = (base + 0 < n_blocks) ? g_spine[base + 0] : 0;
    int v1 = (base + 1 < n_blocks) ? g_spine[base + 1] : 0;
    int v2 = (base + 2 < n_blocks) ? g_spine[base + 2] : 0;
    int v3 = (base + 3 < n_blocks) ? g_spine[base + 3] : 0;
    const int s1 = v0 + v1, s2 = s1 + v2, tot = s2 + v3;
    int incl = tot;
    #pragma unroll
    for (int off = 1; off < 32; off <<= 1) {
        int t = __shfl_up_sync(0xffffffffu, incl, off);
        if (lane >= off) incl += t;
    }
    const int excl = incl - tot;
    if (base + 0 < n_blocks) g_spine[base + 0] = excl;
    if (base + 1 < n_blocks) g_spine[base + 1] = excl + v0;
    if (base + 2 < n_blocks) g_spine[base + 2] = excl + s1;
    if (base + 3 < n_blocks) g_spine[base + 3] = excl + s2;
}

// Add spine; initialize cursors.
__global__ void __launch_bounds__(SCAN_B)
csr_scan3(int n)
{
    int i = blockIdx.x * SCAN_B + threadIdx.x;
    if (i < n) {
        int o = g_offsets[i] + g_spine[blockIdx.x];
        g_offsets[i] = o;
        g_cursor[i]  = o;
    }
}

__global__ void csr_scatter(const int* __restrict__ src,
                            const int* __restrict__ dst,
                            const float* __restrict__ w,
                            int n_edges)
{
    int i = (blockIdx.x * blockDim.x + threadIdx.x) * 4;
    if (i + 3 < n_edges) {
        const int4   s4 = *reinterpret_cast<const int4*>(src + i);
        const int4   d4 = *reinterpret_cast<const int4*>(dst + i);
        const float4 w4 = *reinterpret_cast<const float4*>(w + i);
        int p;
        p = atomicAdd(&g_cursor[d4.x], 1); g_edge[p] = make_int4(s4.x, __float_as_int(w4.x), d4.x, 0);
        p = atomicAdd(&g_cursor[d4.y], 1); g_edge[p] = make_int4(s4.y, __float_as_int(w4.y), d4.y, 0);
        p = atomicAdd(&g_cursor[d4.z], 1); g_edge[p] = make_int4(s4.z, __float_as_int(w4.z), d4.z, 0);
        p = atomicAdd(&g_cursor[d4.w], 1); g_edge[p] = make_int4(s4.w, __float_as_int(w4.w), d4.w, 0);
    } else {
        for (; i < n_edges; ++i) {
            int p = atomicAdd(&g_cursor[dst[i]], 1);
            g_edge[p] = make_int4(src[i], __float_as_int(w[i]), dst[i], 0);
        }
    }
}

// ---------------------------------------------------------------------------
// Kernel 2: one hop, equal-work chunks over the dst-sorted edge list.
// 8-thread group owns CHUNK consecutive edges; thread c owns the c-th 16B
// chunk of the embedding row. Register-accumulate across same-dst runs,
// flush with red.v4 at dst boundaries. Perfect load balance; ~1.6M REDs/hop
// instead of 12.8M. h_out must be pre-zeroed.
// ---------------------------------------------------------------------------
__global__ void __launch_bounds__(256)
sgc_hop_chunk(const float* __restrict__ h_in,
              float* __restrict__ h_out,
              int n_edges)
{
    const int gid = blockIdx.x * blockDim.x + threadIdx.x;
    const int grp = gid >> 3;
    const int c   = gid & 7;
    const int e0  = grp * CHUNK;
    if (e0 >= n_edges) return;
    const int e1 = min(e0 + CHUNK, n_edges);

    float4 acc = make_float4(0.f, 0.f, 0.f, 0.f);
    int cur = g_edge[e0].z;

    #pragma unroll 4
    for (int j = e0; j < e1; ++j) {
        const int4 ed = g_edge[j];
        if (ed.z != cur) {
            float* p = h_out + (size_t)cur * EMB_DIM + (size_t)c * 4;
            asm volatile("red.global.add.v4.f32 [%0], {%1, %2, %3, %4};"
                         :: "l"(p), "f"(acc.x), "f"(acc.y), "f"(acc.z), "f"(acc.w)
                         : "memory");
            acc = make_float4(0.f, 0.f, 0.f, 0.f);
            cur = ed.z;
        }
        const float wv = __int_as_float(ed.y);
        const float4 v = reinterpret_cast<const float4*>(h_in + (size_t)ed.x * EMB_DIM)[c];
        acc.x = fmaf(v.x, wv, acc.x);
        acc.y = fmaf(v.y, wv, acc.y);
        acc.z = fmaf(v.z, wv, acc.z);
        acc.w = fmaf(v.w, wv, acc.w);
    }
    float* p = h_out + (size_t)cur * EMB_DIM + (size_t)c * 4;
    asm volatile("red.global.add.v4.f32 [%0], {%1, %2, %3, %4};"
                 :: "l"(p), "f"(acc.x), "f"(acc.y), "f"(acc.z), "f"(acc.w)
                 : "memory");
}

// ---------------------------------------------------------------------------
// Launcher. Inputs: x[N,128] f32, W[32,128] f32, b[32] f32, w[E] f32,
// src[E] i32, dst[E] i32, k (fixed 3). Output: h[N,32] f32.
// ---------------------------------------------------------------------------
extern "C" void kernel_launch(void* const* d_in, const int* in_sizes, int n_in,
                              void* d_out, int out_size)
{
    const float* x   = (const float*)d_in[0];
    const float* W   = (const float*)d_in[1];
    const float* b   = (const float*)d_in[2];
    const float* w   = (const float*)d_in[3];
    const int*   src = (const int*)d_in[4];
    const int*   dst = (const int*)d_in[5];
    float* out = (float*)d_out;

    const int n_nodes = in_sizes[0] / IN_DIM;
    const int n_edges = in_sizes[3];
    const size_t h_bytes = (size_t)n_nodes * EMB_DIM * sizeof(float);

    float* hA = nullptr; float* hB = nullptr; int* counts = nullptr;
    cudaGetSymbolAddress((void**)&hA, g_hA);
    cudaGetSymbolAddress((void**)&hB, g_hB);
    cudaGetSymbolAddress((void**)&counts, g_counts);

    // Transform: h0 = relu(x @ W^T + b) -> hA
    sgc_transform<<<(n_nodes + 255) / 256, 256>>>(x, W, b, hA, n_nodes);

    // CSR build (per call; no caching allowed).
    cudaMemsetAsync(counts, 0, (size_t)n_nodes * sizeof(int));
    csr_histogram<<<(n_edges / 4 + 255) / 256, 256>>>(dst, n_edges);
    const int scan_blocks = (n_nodes + SCAN_B - 1) / SCAN_B;
    csr_scan1<<<scan_blocks, SCAN_B>>>(n_nodes);
    csr_scan2<<<1, 32>>>(scan_blocks);
    csr_scan3<<<scan_blocks, SCAN_B>>>(n_nodes);
    csr_scatter<<<(n_edges / 4 + 255) / 256, 256>>>(src, dst, w, n_edges);

    // 3 hops, equal-work chunked gather + boundary REDs.
    const long long n_grp = ((long long)n_edges + CHUNK - 1) / CHUNK;
    const int hop_blocks = (int)((n_grp * 8 + 255) / 256);

    cudaMemsetAsync(hB, 0, h_bytes);
    sgc_hop_chunk<<<hop_blocks, 256>>>(hA, hB, n_edges);

    cudaMemsetAsync(hA, 0, h_bytes);
    sgc_hop_chunk<<<hop_blocks, 256>>>(hB, hA, n_edges);

    cudaMemsetAsync(out, 0, (size_t)out_size * sizeof(float));
    sgc_hop_chunk<<<hop_blocks, 256>>>(hA, out, n_edges);
}

// round 6
// speedup vs baseline: 2.8258x; 1.1358x over previous
#include <cuda_runtime.h>
#include <cstdint>

// Problem constants (SGC_77584289235646): fixed shapes.
#define IN_DIM    128
#define EMB_DIM   32
#define MAX_NODES 100000
#define MAX_EDGES 1600000
#define SCAN_B    1024
#define MAX_SCAN_BLOCKS 128
#define CHUNK     16            // edges per 8-thread group in the hop

// Scratch (no cudaMalloc allowed).
__device__ __align__(16) float g_hA[(size_t)MAX_NODES * EMB_DIM];
__device__ __align__(16) float g_hB[(size_t)MAX_NODES * EMB_DIM];
__device__ int  g_counts [MAX_NODES];
__device__ int  g_offsets[MAX_NODES];
__device__ int  g_cursor [MAX_NODES];
__device__ int  g_spine  [MAX_SCAN_BLOCKS];
__device__ __align__(16) int4 g_edge[MAX_EDGES];   // {src, w-bits, dst, 0} sorted by dst

// ---------------------------------------------------------------------------
// Kernel 1: h0 = relu(x @ W^T + b). Thread-per-node, 32 accumulators,
// W staged in smem (broadcast LDS.128). FFMA-bound (~25us).
// ---------------------------------------------------------------------------
__global__ void __launch_bounds__(256)
sgc_transform(const float* __restrict__ x,
              const float* __restrict__ W,
              const float* __restrict__ b,
              float* __restrict__ h,
              int n_nodes)
{
    __shared__ float4 Ws[EMB_DIM * (IN_DIM / 4)];   // 16KB
    __shared__ float  bsh[EMB_DIM];

    for (int i = threadIdx.x; i < EMB_DIM * (IN_DIM / 4); i += blockDim.x)
        Ws[i] = reinterpret_cast<const float4*>(W)[i];
    if (threadIdx.x < EMB_DIM) bsh[threadIdx.x] = b[threadIdx.x];
    __syncthreads();

    const int node = blockIdx.x * blockDim.x + threadIdx.x;
    if (node >= n_nodes) return;

    const float4* xr = reinterpret_cast<const float4*>(x + (size_t)node * IN_DIM);

    float acc[EMB_DIM];
    #pragma unroll
    for (int e = 0; e < EMB_DIM; ++e) acc[e] = 0.f;

    #pragma unroll 4
    for (int kc = 0; kc < IN_DIM / 4; ++kc) {
        const float4 xv = xr[kc];
        #pragma unroll
        for (int e = 0; e < EMB_DIM; ++e) {
            const float4 wv = Ws[e * (IN_DIM / 4) + kc];
            acc[e] = fmaf(xv.x, wv.x, acc[e]);
            acc[e] = fmaf(xv.y, wv.y, acc[e]);
            acc[e] = fmaf(xv.z, wv.z, acc[e]);
            acc[e] = fmaf(xv.w, wv.w, acc[e]);
        }
    }

    float4* hp = reinterpret_cast<float4*>(h + (size_t)node * EMB_DIM);
    #pragma unroll
    for (int e = 0; e < EMB_DIM; e += 4) {
        float4 o;
        o.x = fmaxf(acc[e + 0] + bsh[e + 0], 0.f);
        o.y = fmaxf(acc[e + 1] + bsh[e + 1], 0.f);
        o.z = fmaxf(acc[e + 2] + bsh[e + 2], 0.f);
        o.w = fmaxf(acc[e + 3] + bsh[e + 3], 0.f);
        hp[e / 4] = o;
    }
}

// ---------------------------------------------------------------------------
// CSR build: histogram -> scan1 (block scan) -> scan3 (spine-fused) -> scatter
// ---------------------------------------------------------------------------
__global__ void csr_histogram(const int* __restrict__ dst, int n_edges)
{
    int i = (blockIdx.x * blockDim.x + threadIdx.x) * 4;
    if (i + 3 < n_edges) {
        const int4 d = *reinterpret_cast<const int4*>(dst + i);
        atomicAdd(&g_counts[d.x], 1);
        atomicAdd(&g_counts[d.y], 1);
        atomicAdd(&g_counts[d.z], 1);
        atomicAdd(&g_counts[d.w], 1);
    } else {
        for (; i < n_edges; ++i) atomicAdd(&g_counts[dst[i]], 1);
    }
}

// Block-local exclusive scan via warp shuffles; block totals -> spine.
__global__ void __launch_bounds__(SCAN_B)
csr_scan1(int n)
{
    __shared__ int wsum[32];
    const int i    = blockIdx.x * SCAN_B + threadIdx.x;
    const int lane = threadIdx.x & 31;
    const int warp = threadIdx.x >> 5;

    const int v = (i < n) ? g_counts[i] : 0;
    int incl = v;
    #pragma unroll
    for (int off = 1; off < 32; off <<= 1) {
        int t = __shfl_up_sync(0xffffffffu, incl, off);
        if (lane >= off) incl += t;
    }
    if (lane == 31) wsum[warp] = incl;
    __syncthreads();
    if (warp == 0) {
        int s = wsum[lane];
        int si = s;
        #pragma unroll
        for (int off = 1; off < 32; off <<= 1) {
            int t = __shfl_up_sync(0xffffffffu, si, off);
            if (lane >= off) si += t;
        }
        wsum[lane] = si - s;                       // exclusive warp offset
        if (lane == 31) g_spine[blockIdx.x] = si;  // block total
    }
    __syncthreads();
    if (i < n) g_offsets[i] = incl - v + wsum[warp];
}

// Spine-prefix fused: warp 0 sums g_spine[0..blockIdx), broadcast, add,
// write offsets + cursors. (Replaces the old scan2 + scan3 pair.)
__global__ void __launch_bounds__(SCAN_B)
csr_scan3(int n)
{
    __shared__ int prefix;
    if (threadIdx.x < 32) {
        const int lane = threadIdx.x;
        int s = 0;
        #pragma unroll
        for (int q = 0; q < MAX_SCAN_BLOCKS / 32; ++q) {
            const int idx = q * 32 + lane;
            if (idx < (int)blockIdx.x) s += g_spine[idx];
        }
        #pragma unroll
        for (int off = 16; off > 0; off >>= 1)
            s += __shfl_down_sync(0xffffffffu, s, off);
        if (lane == 0) prefix = s;
    }
    __syncthreads();
    const int i = blockIdx.x * SCAN_B + threadIdx.x;
    if (i < n) {
        const int o = g_offsets[i] + prefix;
        g_offsets[i] = o;
        g_cursor[i]  = o;
    }
}

__global__ void csr_scatter(const int* __restrict__ src,
                            const int* __restrict__ dst,
                            const float* __restrict__ w,
                            int n_edges)
{
    int i = (blockIdx.x * blockDim.x + threadIdx.x) * 4;
    if (i + 3 < n_edges) {
        const int4   s4 = *reinterpret_cast<const int4*>(src + i);
        const int4   d4 = *reinterpret_cast<const int4*>(dst + i);
        const float4 w4 = *reinterpret_cast<const float4*>(w + i);
        int p;
        p = atomicAdd(&g_cursor[d4.x], 1); g_edge[p] = make_int4(s4.x, __float_as_int(w4.x), d4.x, 0);
        p = atomicAdd(&g_cursor[d4.y], 1); g_edge[p] = make_int4(s4.y, __float_as_int(w4.y), d4.y, 0);
        p = atomicAdd(&g_cursor[d4.z], 1); g_edge[p] = make_int4(s4.z, __float_as_int(w4.z), d4.z, 0);
        p = atomicAdd(&g_cursor[d4.w], 1); g_edge[p] = make_int4(s4.w, __float_as_int(w4.w), d4.w, 0);
    } else {
        for (; i < n_edges; ++i) {
            int p = atomicAdd(&g_cursor[dst[i]], 1);
            g_edge[p] = make_int4(src[i], __float_as_int(w[i]), dst[i], 0);
        }
    }
}

// ---------------------------------------------------------------------------
// Kernel 2: one hop, equal-work chunks over the dst-sorted edge list.
// 8-thread group owns CHUNK consecutive edges; thread c owns the c-th 16B
// chunk of the embedding row. Gather via __ldcg (L2-only: h never fits L1).
// Register-accumulate same-dst runs; red.v4 flush at dst boundaries.
// h_out must be pre-zeroed.
// ---------------------------------------------------------------------------
__global__ void __launch_bounds__(256)
sgc_hop_chunk(const float* __restrict__ h_in,
              float* __restrict__ h_out,
              int n_edges)
{
    const int gid = blockIdx.x * blockDim.x + threadIdx.x;
    const int grp = gid >> 3;
    const int c   = gid & 7;
    const int e0  = grp * CHUNK;
    if (e0 >= n_edges) return;
    const int e1 = min(e0 + CHUNK, n_edges);

    float4 acc = make_float4(0.f, 0.f, 0.f, 0.f);
    int cur = g_edge[e0].z;

    #pragma unroll 4
    for (int j = e0; j < e1; ++j) {
        const int4 ed = g_edge[j];
        if (ed.z != cur) {
            float* p = h_out + (size_t)cur * EMB_DIM + (size_t)c * 4;
            asm volatile("red.global.add.v4.f32 [%0], {%1, %2, %3, %4};"
                         :: "l"(p), "f"(acc.x), "f"(acc.y), "f"(acc.z), "f"(acc.w)
                         : "memory");
            acc = make_float4(0.f, 0.f, 0.f, 0.f);
            cur = ed.z;
        }
        const float wv = __int_as_float(ed.y);
        const float4 v = __ldcg(reinterpret_cast<const float4*>(
                              h_in + (size_t)ed.x * EMB_DIM) + c);
        acc.x = fmaf(v.x, wv, acc.x);
        acc.y = fmaf(v.y, wv, acc.y);
        acc.z = fmaf(v.z, wv, acc.z);
        acc.w = fmaf(v.w, wv, acc.w);
    }
    float* p = h_out + (size_t)cur * EMB_DIM + (size_t)c * 4;
    asm volatile("red.global.add.v4.f32 [%0], {%1, %2, %3, %4};"
                 :: "l"(p), "f"(acc.x), "f"(acc.y), "f"(acc.z), "f"(acc.w)
                 : "memory");
}

// ---------------------------------------------------------------------------
// Launcher. Fork/join under graph capture: transform + output memsets run on
// a side stream concurrently with the CSR build chain; joined before hop 1.
// ---------------------------------------------------------------------------
extern "C" void kernel_launch(void* const* d_in, const int* in_sizes, int n_in,
                              void* d_out, int out_size)
{
    const float* x   = (const float*)d_in[0];
    const float* W   = (const float*)d_in[1];
    const float* b   = (const float*)d_in[2];
    const float* w   = (const float*)d_in[3];
    const int*   src = (const int*)d_in[4];
    const int*   dst = (const int*)d_in[5];
    float* out = (float*)d_out;

    const int n_nodes = in_sizes[0] / IN_DIM;
    const int n_edges = in_sizes[3];
    const size_t h_bytes = (size_t)n_nodes * EMB_DIM * sizeof(float);

    float* hA = nullptr; float* hB = nullptr; int* counts = nullptr;
    cudaGetSymbolAddress((void**)&hA, g_hA);
    cudaGetSymbolAddress((void**)&hB, g_hB);
    cudaGetSymbolAddress((void**)&counts, g_counts);

    cudaStream_t s2;
    cudaEvent_t evFork, evJoin;
    cudaStreamCreateWithFlags(&s2, cudaStreamNonBlocking);
    cudaEventCreateWithFlags(&evFork, cudaEventDisableTiming);
    cudaEventCreateWithFlags(&evJoin, cudaEventDisableTiming);

    // Fork side stream off the capture-origin (legacy) stream.
    cudaEventRecord(evFork, 0);
    cudaStreamWaitEvent(s2, evFork, 0);

    // Branch A (s2): transform + zero the hop-1/3 outputs.
    sgc_transform<<<(n_nodes + 255) / 256, 256, 0, s2>>>(x, W, b, hA, n_nodes);
    cudaMemsetAsync(hB, 0, h_bytes, s2);
    cudaMemsetAsync(out, 0, (size_t)out_size * sizeof(float), s2);

    // Branch B (legacy stream): CSR build.
    cudaMemsetAsync(counts, 0, (size_t)n_nodes * sizeof(int));
    csr_histogram<<<(n_edges / 4 + 255) / 256, 256>>>(dst, n_edges);
    const int scan_blocks = (n_nodes + SCAN_B - 1) / SCAN_B;
    csr_scan1<<<scan_blocks, SCAN_B>>>(n_nodes);
    csr_scan3<<<scan_blocks, SCAN_B>>>(n_nodes);
    csr_scatter<<<(n_edges / 4 + 255) / 256, 256>>>(src, dst, w, n_edges);

    // Join.
    cudaEventRecord(evJoin, s2);
    cudaStreamWaitEvent(0, evJoin, 0);

    // 3 hops (legacy stream).
    const long long n_grp = ((long long)n_edges + CHUNK - 1) / CHUNK;
    const int hop_blocks = (int)((n_grp * 8 + 255) / 256);

    sgc_hop_chunk<<<hop_blocks, 256>>>(hA, hB, n_edges);
    cudaMemsetAsync(hA, 0, h_bytes);
    sgc_hop_chunk<<<hop_blocks, 256>>>(hB, hA, n_edges);
    sgc_hop_chunk<<<hop_blocks, 256>>>(hA, out, n_edges);
}

// round 7
// speedup vs baseline: 2.8312x; 1.0019x over previous
#include <cuda_runtime.h>
#include <cstdint>

// Problem constants (SGC_77584289235646): fixed shapes.
#define IN_DIM    128
#define EMB_DIM   32
#define MAX_NODES 100000
#define MAX_EDGES 1600000
#define SCAN_B    1024
#define MAX_SCAN_BLOCKS 128
#define CHUNK     16            // edges per 8-thread group in the hop

// Scratch (no cudaMalloc allowed).
__device__ __align__(16) float g_hA[(size_t)MAX_NODES * EMB_DIM];
__device__ __align__(16) float g_hB[(size_t)MAX_NODES * EMB_DIM];
__device__ int  g_counts [MAX_NODES];
__device__ int  g_offsets[MAX_NODES];
__device__ int  g_cursor [MAX_NODES];
__device__ int  g_spine  [MAX_SCAN_BLOCKS];
__device__ __align__(16) int4 g_edge[MAX_EDGES];   // {src, w-bits, dst, 0} sorted by dst

// ---------------------------------------------------------------------------
// Kernel 1: h0 = relu(x @ W^T + b). Thread-per-node, 32 accumulators,
// W staged in smem (broadcast LDS.128). FFMA-bound (~25us).
// ---------------------------------------------------------------------------
__global__ void __launch_bounds__(256)
sgc_transform(const float* __restrict__ x,
              const float* __restrict__ W,
              const float* __restrict__ b,
              float* __restrict__ h,
              int n_nodes)
{
    __shared__ float4 Ws[EMB_DIM * (IN_DIM / 4)];   // 16KB
    __shared__ float  bsh[EMB_DIM];

    for (int i = threadIdx.x; i < EMB_DIM * (IN_DIM / 4); i += blockDim.x)
        Ws[i] = reinterpret_cast<const float4*>(W)[i];
    if (threadIdx.x < EMB_DIM) bsh[threadIdx.x] = b[threadIdx.x];
    __syncthreads();

    const int node = blockIdx.x * blockDim.x + threadIdx.x;
    if (node >= n_nodes) return;

    const float4* xr = reinterpret_cast<const float4*>(x + (size_t)node * IN_DIM);

    float acc[EMB_DIM];
    #pragma unroll
    for (int e = 0; e < EMB_DIM; ++e) acc[e] = 0.f;

    #pragma unroll 4
    for (int kc = 0; kc < IN_DIM / 4; ++kc) {
        const float4 xv = xr[kc];
        #pragma unroll
        for (int e = 0; e < EMB_DIM; ++e) {
            const float4 wv = Ws[e * (IN_DIM / 4) + kc];
            acc[e] = fmaf(xv.x, wv.x, acc[e]);
            acc[e] = fmaf(xv.y, wv.y, acc[e]);
            acc[e] = fmaf(xv.z, wv.z, acc[e]);
            acc[e] = fmaf(xv.w, wv.w, acc[e]);
        }
    }

    float4* hp = reinterpret_cast<float4*>(h + (size_t)node * EMB_DIM);
    #pragma unroll
    for (int e = 0; e < EMB_DIM; e += 4) {
        float4 o;
        o.x = fmaxf(acc[e + 0] + bsh[e + 0], 0.f);
        o.y = fmaxf(acc[e + 1] + bsh[e + 1], 0.f);
        o.z = fmaxf(acc[e + 2] + bsh[e + 2], 0.f);
        o.w = fmaxf(acc[e + 3] + bsh[e + 3], 0.f);
        hp[e / 4] = o;
    }
}

// ---------------------------------------------------------------------------
// CSR build: histogram -> scan1 (block scan) -> scan3 (spine-fused) -> scatter
// ---------------------------------------------------------------------------
__global__ void csr_histogram(const int* __restrict__ dst, int n_edges)
{
    int i = (blockIdx.x * blockDim.x + threadIdx.x) * 4;
    if (i + 3 < n_edges) {
        const int4 d = *reinterpret_cast<const int4*>(dst + i);
        atomicAdd(&g_counts[d.x], 1);
        atomicAdd(&g_counts[d.y], 1);
        atomicAdd(&g_counts[d.z], 1);
        atomicAdd(&g_counts[d.w], 1);
    } else {
        for (; i < n_edges; ++i) atomicAdd(&g_counts[dst[i]], 1);
    }
}

// Block-local exclusive scan via warp shuffles; block totals -> spine.
__global__ void __launch_bounds__(SCAN_B)
csr_scan1(int n)
{
    __shared__ int wsum[32];
    const int i    = blockIdx.x * SCAN_B + threadIdx.x;
    const int lane = threadIdx.x & 31;
    const int warp = threadIdx.x >> 5;

    const int v = (i < n) ? g_counts[i] : 0;
    int incl = v;
    #pragma unroll
    for (int off = 1; off < 32; off <<= 1) {
        int t = __shfl_up_sync(0xffffffffu, incl, off);
        if (lane >= off) incl += t;
    }
    if (lane == 31) wsum[warp] = incl;
    __syncthreads();
    if (warp == 0) {
        int s = wsum[lane];
        int si = s;
        #pragma unroll
        for (int off = 1; off < 32; off <<= 1) {
            int t = __shfl_up_sync(0xffffffffu, si, off);
            if (lane >= off) si += t;
        }
        wsum[lane] = si - s;                       // exclusive warp offset
        if (lane == 31) g_spine[blockIdx.x] = si;  // block total
    }
    __syncthreads();
    if (i < n) g_offsets[i] = incl - v + wsum[warp];
}

// Spine-prefix fused: warp 0 sums g_spine[0..blockIdx), broadcast, add,
// write offsets + cursors. (Replaces the old scan2 + scan3 pair.)
__global__ void __launch_bounds__(SCAN_B)
csr_scan3(int n)
{
    __shared__ int prefix;
    if (threadIdx.x < 32) {
        const int lane = threadIdx.x;
        int s = 0;
        #pragma unroll
        for (int q = 0; q < MAX_SCAN_BLOCKS / 32; ++q) {
            const int idx = q * 32 + lane;
            if (idx < (int)blockIdx.x) s += g_spine[idx];
        }
        #pragma unroll
        for (int off = 16; off > 0; off >>= 1)
            s += __shfl_down_sync(0xffffffffu, s, off);
        if (lane == 0) prefix = s;
    }
    __syncthreads();
    const int i = blockIdx.x * SCAN_B + threadIdx.x;
    if (i < n) {
        const int o = g_offsets[i] + prefix;
        g_offsets[i] = o;
        g_cursor[i]  = o;
    }
}

__global__ void csr_scatter(const int* __restrict__ src,
                            const int* __restrict__ dst,
                            const float* __restrict__ w,
                            int n_edges)
{
    int i = (blockIdx.x * blockDim.x + threadIdx.x) * 4;
    if (i + 3 < n_edges) {
        const int4   s4 = *reinterpret_cast<const int4*>(src + i);
        const int4   d4 = *reinterpret_cast<const int4*>(dst + i);
        const float4 w4 = *reinterpret_cast<const float4*>(w + i);
        int p;
        p = atomicAdd(&g_cursor[d4.x], 1); g_edge[p] = make_int4(s4.x, __float_as_int(w4.x), d4.x, 0);
        p = atomicAdd(&g_cursor[d4.y], 1); g_edge[p] = make_int4(s4.y, __float_as_int(w4.y), d4.y, 0);
        p = atomicAdd(&g_cursor[d4.z], 1); g_edge[p] = make_int4(s4.z, __float_as_int(w4.z), d4.z, 0);
        p = atomicAdd(&g_cursor[d4.w], 1); g_edge[p] = make_int4(s4.w, __float_as_int(w4.w), d4.w, 0);
    } else {
        for (; i < n_edges; ++i) {
            int p = atomicAdd(&g_cursor[dst[i]], 1);
            g_edge[p] = make_int4(src[i], __float_as_int(w[i]), dst[i], 0);
        }
    }
}

// ---------------------------------------------------------------------------
// Kernel 2: one hop, equal-work chunks over the dst-sorted edge list.
// 8-thread group owns CHUNK consecutive edges; thread c owns the c-th 16B
// chunk of the embedding row. Gather via __ldcg (L2-only: h never fits L1).
// Register-accumulate same-dst runs; red.v4 flush at dst boundaries.
// h_out must be pre-zeroed.
// ---------------------------------------------------------------------------
__global__ void __launch_bounds__(256)
sgc_hop_chunk(const float* __restrict__ h_in,
              float* __restrict__ h_out,
              int n_edges)
{
    const int gid = blockIdx.x * blockDim.x + threadIdx.x;
    const int grp = gid >> 3;
    const int c   = gid & 7;
    const int e0  = grp * CHUNK;
    if (e0 >= n_edges) return;
    const int e1 = min(e0 + CHUNK, n_edges);

    float4 acc = make_float4(0.f, 0.f, 0.f, 0.f);
    int cur = g_edge[e0].z;

    #pragma unroll 4
    for (int j = e0; j < e1; ++j) {
        const int4 ed = g_edge[j];
        if (ed.z != cur) {
            float* p = h_out + (size_t)cur * EMB_DIM + (size_t)c * 4;
            asm volatile("red.global.add.v4.f32 [%0], {%1, %2, %3, %4};"
                         :: "l"(p), "f"(acc.x), "f"(acc.y), "f"(acc.z), "f"(acc.w)
                         : "memory");
            acc = make_float4(0.f, 0.f, 0.f, 0.f);
            cur = ed.z;
        }
        const float wv = __int_as_float(ed.y);
        const float4 v = __ldcg(reinterpret_cast<const float4*>(
                              h_in + (size_t)ed.x * EMB_DIM) + c);
        acc.x = fmaf(v.x, wv, acc.x);
        acc.y = fmaf(v.y, wv, acc.y);
        acc.z = fmaf(v.z, wv, acc.z);
        acc.w = fmaf(v.w, wv, acc.w);
    }
    float* p = h_out + (size_t)cur * EMB_DIM + (size_t)c * 4;
    asm volatile("red.global.add.v4.f32 [%0], {%1, %2, %3, %4};"
                 :: "l"(p), "f"(acc.x), "f"(acc.y), "f"(acc.z), "f"(acc.w)
                 : "memory");
}

// ---------------------------------------------------------------------------
// Launcher. Fork/join under graph capture: transform + output memsets run on
// a side stream concurrently with the CSR build chain; joined before hop 1.
// ---------------------------------------------------------------------------
extern "C" void kernel_launch(void* const* d_in, const int* in_sizes, int n_in,
                              void* d_out, int out_size)
{
    const float* x   = (const float*)d_in[0];
    const float* W   = (const float*)d_in[1];
    const float* b   = (const float*)d_in[2];
    const float* w   = (const float*)d_in[3];
    const int*   src = (const int*)d_in[4];
    const int*   dst = (const int*)d_in[5];
    float* out = (float*)d_out;

    const int n_nodes = in_sizes[0] / IN_DIM;
    const int n_edges = in_sizes[3];
    const size_t h_bytes = (size_t)n_nodes * EMB_DIM * sizeof(float);

    float* hA = nullptr; float* hB = nullptr; int* counts = nullptr;
    cudaGetSymbolAddress((void**)&hA, g_hA);
    cudaGetSymbolAddress((void**)&hB, g_hB);
    cudaGetSymbolAddress((void**)&counts, g_counts);

    cudaStream_t s2;
    cudaEvent_t evFork, evJoin;
    cudaStreamCreateWithFlags(&s2, cudaStreamNonBlocking);
    cudaEventCreateWithFlags(&evFork, cudaEventDisableTiming);
    cudaEventCreateWithFlags(&evJoin, cudaEventDisableTiming);

    // Fork side stream off the capture-origin (legacy) stream.
    cudaEventRecord(evFork, 0);
    cudaStreamWaitEvent(s2, evFork, 0);

    // Branch A (s2): transform + zero the hop-1/3 outputs.
    sgc_transform<<<(n_nodes + 255) / 256, 256, 0, s2>>>(x, W, b, hA, n_nodes);
    cudaMemsetAsync(hB, 0, h_bytes, s2);
    cudaMemsetAsync(out, 0, (size_t)out_size * sizeof(float), s2);

    // Branch B (legacy stream): CSR build.
    cudaMemsetAsync(counts, 0, (size_t)n_nodes * sizeof(int));
    csr_histogram<<<(n_edges / 4 + 255) / 256, 256>>>(dst, n_edges);
    const int scan_blocks = (n_nodes + SCAN_B - 1) / SCAN_B;
    csr_scan1<<<scan_blocks, SCAN_B>>>(n_nodes);
    csr_scan3<<<scan_blocks, SCAN_B>>>(n_nodes);
    csr_scatter<<<(n_edges / 4 + 255) / 256, 256>>>(src, dst, w, n_edges);

    // Join.
    cudaEventRecord(evJoin, s2);
    cudaStreamWaitEvent(0, evJoin, 0);

    // 3 hops (legacy stream).
    const long long n_grp = ((long long)n_edges + CHUNK - 1) / CHUNK;
    const int hop_blocks = (int)((n_grp * 8 + 255) / 256);

    sgc_hop_chunk<<<hop_blocks, 256>>>(hA, hB, n_edges);
    cudaMemsetAsync(hA, 0, h_bytes);
    sgc_hop_chunk<<<hop_blocks, 256>>>(hB, hA, n_edges);
    sgc_hop_chunk<<<hop_blocks, 256>>>(hA, out, n_edges);
}